// round 1
// baseline (speedup 1.0000x reference)
#include <cuda_runtime.h>
#include <cstdint>

#define B_  8
#define C_  256
#define N_  2048
#define D_  32

// Scratch (device-global: allocation-free per harness rules)
__device__ float g_q[(size_t)B_ * D_ * N_];          // (B, D, N)
__device__ float g_k[(size_t)B_ * D_ * N_];          // (B, D, N)
__device__ float g_v[(size_t)B_ * C_ * N_];          // (B, C, N)
__device__ float g_p[(size_t)B_ * N_ * N_];          // (B, N, N) logits -> probs

// ---------------------------------------------------------------------------
// Projection: out[b][m][n] = sum_c W[m][c] * x[b][c][n] + bias[m]
// Tile: BM=32, BN=128, BK=32. 256 threads, 4x4 microtile per thread.
// grid = (N/128, M/32, B)
// ---------------------------------------------------------------------------
__global__ __launch_bounds__(256) void proj_kernel(
    const float* __restrict__ W, const float* __restrict__ bias,
    const float* __restrict__ x, float* __restrict__ out, int M)
{
    __shared__ float Ws[32][32];    // Ws[kk][m]
    __shared__ float Xs[32][128];   // Xs[kk][n]

    const int b   = blockIdx.z;
    const int m0  = blockIdx.y * 32;
    const int n0  = blockIdx.x * 128;
    const int tid = threadIdx.x;
    const int tr  = tid >> 5;   // 0..7  -> rows tr*4..tr*4+3
    const int tc  = tid & 31;   // 0..31 -> cols tc*4..tc*4+3

    const float* xb = x + (size_t)b * C_ * N_;

    float acc[4][4] = {};

    for (int c0 = 0; c0 < C_; c0 += 32) {
        // W tile (transposed into smem)
        {
            const int r  = tid >> 3;        // 0..31
            const int k4 = (tid & 7) * 4;   // 0..28
            const float4 w4 = *(const float4*)(W + (size_t)(m0 + r) * C_ + c0 + k4);
            Ws[k4 + 0][r] = w4.x; Ws[k4 + 1][r] = w4.y;
            Ws[k4 + 2][r] = w4.z; Ws[k4 + 3][r] = w4.w;
        }
        // X tile
        #pragma unroll
        for (int p = 0; p < 4; p++) {
            const int kk  = p * 8 + (tid >> 5);
            const int col = (tid & 31) * 4;
            *(float4*)&Xs[kk][col] =
                *(const float4*)(xb + (size_t)(c0 + kk) * N_ + n0 + col);
        }
        __syncthreads();

        #pragma unroll
        for (int kk = 0; kk < 32; kk++) {
            const float4 wf = *(const float4*)&Ws[kk][tr * 4];
            const float4 xf = *(const float4*)&Xs[kk][tc * 4];
            acc[0][0] += wf.x * xf.x; acc[0][1] += wf.x * xf.y; acc[0][2] += wf.x * xf.z; acc[0][3] += wf.x * xf.w;
            acc[1][0] += wf.y * xf.x; acc[1][1] += wf.y * xf.y; acc[1][2] += wf.y * xf.z; acc[1][3] += wf.y * xf.w;
            acc[2][0] += wf.z * xf.x; acc[2][1] += wf.z * xf.y; acc[2][2] += wf.z * xf.z; acc[2][3] += wf.z * xf.w;
            acc[3][0] += wf.w * xf.x; acc[3][1] += wf.w * xf.y; acc[3][2] += wf.w * xf.z; acc[3][3] += wf.w * xf.w;
        }
        __syncthreads();
    }

    #pragma unroll
    for (int i = 0; i < 4; i++) {
        const int m = m0 + tr * 4 + i;
        const float bm = bias[m];
        float4 o;
        o.x = acc[i][0] + bm; o.y = acc[i][1] + bm;
        o.z = acc[i][2] + bm; o.w = acc[i][3] + bm;
        *(float4*)(out + ((size_t)b * M + m) * N_ + n0 + tc * 4) = o;
    }
}

// ---------------------------------------------------------------------------
// Energy: e[b][i][j] = sum_d q[b][d][i] * k[b][d][j]
// Tile 64x64, K=32 (single chunk). 256 threads, 4x4 microtile.
// grid = (N/64, N/64, B)
// ---------------------------------------------------------------------------
__global__ __launch_bounds__(256) void energy_kernel(
    const float* __restrict__ q, const float* __restrict__ k,
    float* __restrict__ p)
{
    __shared__ float qs[32][64];
    __shared__ float ks[32][64];

    const int b   = blockIdx.z;
    const int i0  = blockIdx.y * 64;
    const int j0  = blockIdx.x * 64;
    const int tid = threadIdx.x;
    const int tr  = tid >> 4;   // 0..15 -> rows tr*4..
    const int tc  = tid & 15;   // 0..15 -> cols tc*4..

    const float* qb = q + (size_t)b * D_ * N_;
    const float* kb = k + (size_t)b * D_ * N_;

    #pragma unroll
    for (int ps = 0; ps < 2; ps++) {
        const int d   = ps * 16 + (tid >> 4);
        const int col = (tid & 15) * 4;
        *(float4*)&qs[d][col] = *(const float4*)(qb + (size_t)d * N_ + i0 + col);
        *(float4*)&ks[d][col] = *(const float4*)(kb + (size_t)d * N_ + j0 + col);
    }
    __syncthreads();

    float acc[4][4] = {};
    #pragma unroll
    for (int d = 0; d < 32; d++) {
        const float4 a = *(const float4*)&qs[d][tr * 4];
        const float4 c = *(const float4*)&ks[d][tc * 4];
        acc[0][0] += a.x * c.x; acc[0][1] += a.x * c.y; acc[0][2] += a.x * c.z; acc[0][3] += a.x * c.w;
        acc[1][0] += a.y * c.x; acc[1][1] += a.y * c.y; acc[1][2] += a.y * c.z; acc[1][3] += a.y * c.w;
        acc[2][0] += a.z * c.x; acc[2][1] += a.z * c.y; acc[2][2] += a.z * c.z; acc[2][3] += a.z * c.w;
        acc[3][0] += a.w * c.x; acc[3][1] += a.w * c.y; acc[3][2] += a.w * c.z; acc[3][3] += a.w * c.w;
    }

    float* pb = p + (size_t)b * N_ * N_;
    #pragma unroll
    for (int i = 0; i < 4; i++) {
        *(float4*)(pb + (size_t)(i0 + tr * 4 + i) * N_ + j0 + tc * 4) =
            *(float4*)acc[i];
    }
}

// ---------------------------------------------------------------------------
// Softmax over last dim, in place on g_p. One 256-thread block per row.
// grid = (N, B)
// ---------------------------------------------------------------------------
__global__ __launch_bounds__(256) void softmax_kernel(float* __restrict__ p)
{
    float* pr = p + ((size_t)blockIdx.y * N_ + blockIdx.x) * N_;
    const int tid = threadIdx.x;

    float4 v0 = ((const float4*)pr)[tid];
    float4 v1 = ((const float4*)pr)[tid + 256];

    float m = fmaxf(fmaxf(fmaxf(v0.x, v0.y), fmaxf(v0.z, v0.w)),
                    fmaxf(fmaxf(v1.x, v1.y), fmaxf(v1.z, v1.w)));
    #pragma unroll
    for (int o = 16; o > 0; o >>= 1)
        m = fmaxf(m, __shfl_xor_sync(0xFFFFFFFFu, m, o));

    __shared__ float red[8];
    if ((tid & 31) == 0) red[tid >> 5] = m;
    __syncthreads();
    float bm = red[0];
    #pragma unroll
    for (int w = 1; w < 8; w++) bm = fmaxf(bm, red[w]);
    __syncthreads();

    float4 e0, e1;
    e0.x = __expf(v0.x - bm); e0.y = __expf(v0.y - bm);
    e0.z = __expf(v0.z - bm); e0.w = __expf(v0.w - bm);
    e1.x = __expf(v1.x - bm); e1.y = __expf(v1.y - bm);
    e1.z = __expf(v1.z - bm); e1.w = __expf(v1.w - bm);

    float s = e0.x + e0.y + e0.z + e0.w + e1.x + e1.y + e1.z + e1.w;
    #pragma unroll
    for (int o = 16; o > 0; o >>= 1)
        s += __shfl_xor_sync(0xFFFFFFFFu, s, o);
    if ((tid & 31) == 0) red[tid >> 5] = s;
    __syncthreads();
    float bs = 0.f;
    #pragma unroll
    for (int w = 0; w < 8; w++) bs += red[w];

    const float inv = 1.0f / bs;
    e0.x *= inv; e0.y *= inv; e0.z *= inv; e0.w *= inv;
    e1.x *= inv; e1.y *= inv; e1.z *= inv; e1.w *= inv;
    ((float4*)pr)[tid]       = e0;
    ((float4*)pr)[tid + 256] = e1;
}

// ---------------------------------------------------------------------------
// Out GEMM + epilogue:
//   out[b][m][i] = gamma * sum_j v[b][m][j] * P[b][i][j] + x[b][m][i]
// Tile: BM=128 (m), BN=128 (i), BK=16 (j). 256 threads, 8x8 microtile.
// grid = (N/128, C/128, B)
// ---------------------------------------------------------------------------
__global__ __launch_bounds__(256) void out_kernel(
    const float* __restrict__ v, const float* __restrict__ p,
    const float* __restrict__ x, const float* __restrict__ gamma,
    float* __restrict__ out)
{
    __shared__ float As[16][132];   // As[kk][m]   (v, transposed)
    __shared__ float Bs[16][132];   // Bs[kk][i]   (P, transposed)

    const int b   = blockIdx.z;
    const int m0  = blockIdx.y * 128;
    const int i0  = blockIdx.x * 128;
    const int tid = threadIdx.x;
    const int tr  = tid >> 4;   // 0..15 -> rows tr*8..
    const int tc  = tid & 15;   // 0..15 -> cols tc*8..

    const float* vb = v + (size_t)b * C_ * N_;
    const float* pb = p + (size_t)b * N_ * N_;

    float acc[8][8] = {};

    for (int j0 = 0; j0 < N_; j0 += 16) {
        #pragma unroll
        for (int ps = 0; ps < 2; ps++) {
            const int r  = ps * 64 + (tid >> 2);   // 0..127
            const int k4 = (tid & 3) * 4;          // 0..12
            const float4 a4 = *(const float4*)(vb + (size_t)(m0 + r) * N_ + j0 + k4);
            As[k4 + 0][r] = a4.x; As[k4 + 1][r] = a4.y;
            As[k4 + 2][r] = a4.z; As[k4 + 3][r] = a4.w;
            const float4 b4 = *(const float4*)(pb + (size_t)(i0 + r) * N_ + j0 + k4);
            Bs[k4 + 0][r] = b4.x; Bs[k4 + 1][r] = b4.y;
            Bs[k4 + 2][r] = b4.z; Bs[k4 + 3][r] = b4.w;
        }
        __syncthreads();

        #pragma unroll
        for (int kk = 0; kk < 16; kk++) {
            float af[8], bf[8];
            *(float4*)(af)     = *(const float4*)&As[kk][tr * 8];
            *(float4*)(af + 4) = *(const float4*)&As[kk][tr * 8 + 4];
            *(float4*)(bf)     = *(const float4*)&Bs[kk][tc * 8];
            *(float4*)(bf + 4) = *(const float4*)&Bs[kk][tc * 8 + 4];
            #pragma unroll
            for (int i = 0; i < 8; i++)
                #pragma unroll
                for (int j = 0; j < 8; j++)
                    acc[i][j] += af[i] * bf[j];
        }
        __syncthreads();
    }

    const float g = *gamma;
    #pragma unroll
    for (int i = 0; i < 8; i++) {
        const size_t base = ((size_t)b * C_ + (m0 + tr * 8 + i)) * N_ + i0 + tc * 8;
        const float4 x0 = *(const float4*)(x + base);
        const float4 x1 = *(const float4*)(x + base + 4);
        float4 o0, o1;
        o0.x = g * acc[i][0] + x0.x; o0.y = g * acc[i][1] + x0.y;
        o0.z = g * acc[i][2] + x0.z; o0.w = g * acc[i][3] + x0.w;
        o1.x = g * acc[i][4] + x1.x; o1.y = g * acc[i][5] + x1.y;
        o1.z = g * acc[i][6] + x1.z; o1.w = g * acc[i][7] + x1.w;
        *(float4*)(out + base)     = o0;
        *(float4*)(out + base + 4) = o1;
    }
}

// ---------------------------------------------------------------------------
// Launch
// ---------------------------------------------------------------------------
extern "C" void kernel_launch(void* const* d_in, const int* in_sizes, int n_in,
                              void* d_out, int out_size)
{
    const float* x     = (const float*)d_in[0];
    const float* wq    = (const float*)d_in[1];
    const float* bq    = (const float*)d_in[2];
    const float* wk    = (const float*)d_in[3];
    const float* bk    = (const float*)d_in[4];
    const float* wv    = (const float*)d_in[5];
    const float* bv    = (const float*)d_in[6];
    const float* gamma = (const float*)d_in[7];
    float* out = (float*)d_out;

    float *pq, *pk, *pv, *pp;
    cudaGetSymbolAddress((void**)&pq, g_q);
    cudaGetSymbolAddress((void**)&pk, g_k);
    cudaGetSymbolAddress((void**)&pv, g_v);
    cudaGetSymbolAddress((void**)&pp, g_p);

    // Projections
    proj_kernel<<<dim3(N_ / 128, 1, B_), 256>>>(wq, bq, x, pq, D_);
    proj_kernel<<<dim3(N_ / 128, 1, B_), 256>>>(wk, bk, x, pk, D_);
    proj_kernel<<<dim3(N_ / 128, C_ / 32, B_), 256>>>(wv, bv, x, pv, C_);

    // Attention logits
    energy_kernel<<<dim3(N_ / 64, N_ / 64, B_), 256>>>(pq, pk, pp);

    // Softmax
    softmax_kernel<<<dim3(N_, B_), 256>>>(pp);

    // v @ P^T, fused gamma*out + x
    out_kernel<<<dim3(N_ / 128, C_ / 128, B_), 256>>>(pv, pp, x, gamma, out);
}

// round 2
// speedup vs baseline: 3.5720x; 3.5720x over previous
#include <cuda_runtime.h>
#include <cuda_bf16.h>
#include <cstdint>

#define B_  8
#define C_  256
#define N_  2048
#define D_  32

// ---------------------------------------------------------------------------
// Device-global scratch (allocation-free)
// ---------------------------------------------------------------------------
__device__ float          g_p  [(size_t)B_ * N_ * N_];   // fp32 logits
__device__ __nv_bfloat16  g_pbf[(size_t)B_ * N_ * N_];   // bf16 probs
__device__ __nv_bfloat16  g_xt [(size_t)B_ * N_ * C_];   // x^T  (B,N,C) bf16
__device__ __nv_bfloat16  g_qt [(size_t)B_ * N_ * D_];   // q^T  (B,N,D) bf16
__device__ __nv_bfloat16  g_kt [(size_t)B_ * N_ * D_];   // k^T  (B,N,D) bf16
__device__ __nv_bfloat16  g_vbf[(size_t)B_ * C_ * N_];   // v    (B,C,N) bf16
__device__ __nv_bfloat16  g_wvbf[C_ * C_];               // wv bf16

// ---------------------------------------------------------------------------
// PTX helpers
// ---------------------------------------------------------------------------
__device__ __forceinline__ uint32_t smem_u32(const void* p) {
    uint32_t a;
    asm("{ .reg .u64 t; cvta.to.shared.u64 t, %1; cvt.u32.u64 %0, t; }"
        : "=r"(a) : "l"(p));
    return a;
}

__device__ __forceinline__ void ldm_x4(uint32_t* r, uint32_t addr) {
    asm volatile("ldmatrix.sync.aligned.m8n8.x4.shared.b16 {%0,%1,%2,%3}, [%4];\n"
        : "=r"(r[0]), "=r"(r[1]), "=r"(r[2]), "=r"(r[3]) : "r"(addr));
}

__device__ __forceinline__ void mma_bf16(float* d, const uint32_t* a, const uint32_t* b) {
    asm volatile(
        "mma.sync.aligned.m16n8k16.row.col.f32.bf16.bf16.f32 "
        "{%0,%1,%2,%3},{%4,%5,%6,%7},{%8,%9},{%0,%1,%2,%3};\n"
        : "+f"(d[0]), "+f"(d[1]), "+f"(d[2]), "+f"(d[3])
        : "r"(a[0]), "r"(a[1]), "r"(a[2]), "r"(a[3]), "r"(b[0]), "r"(b[1]));
}

#define CP_ASYNC16(saddr, gptr) \
    asm volatile("cp.async.cg.shared.global [%0], [%1], 16;\n" :: "r"(saddr), "l"(gptr))
#define CP_COMMIT() asm volatile("cp.async.commit_group;\n")
#define CP_WAIT0()  asm volatile("cp.async.wait_group 0;\n")

// Shared-tile row stride (bf16 elements): 32 data + 8 pad -> conflict-free ldmatrix
#define SMS 40

// One K=16 step of a 64x32 warp tile: A rows (i/m), B rows (j/n), both [row][k].
__device__ __forceinline__ void mma_tile_step(
    uint32_t sA, uint32_t sB, int kk, int lane, int wm, int wn, float acc[4][4][4])
{
    const int rrow  = lane & 15;
    const int chalf = (lane >> 4) << 3;
    uint32_t a[4][4], bq[2][4];
    #pragma unroll
    for (int mt = 0; mt < 4; mt++)
        ldm_x4(a[mt], sA + (uint32_t)(((wm * 64 + mt * 16 + rrow) * SMS + kk + chalf) * 2));
    #pragma unroll
    for (int np = 0; np < 2; np++)
        ldm_x4(bq[np], sB + (uint32_t)(((wn * 32 + np * 16 + rrow) * SMS + kk + chalf) * 2));
    #pragma unroll
    for (int mt = 0; mt < 4; mt++)
        #pragma unroll
        for (int nt = 0; nt < 4; nt++) {
            uint32_t bb[2] = { bq[nt >> 1][nt & 1], bq[nt >> 1][(nt & 1) + 2] };
            mma_bf16(acc[mt][nt], a[mt], bb);
        }
}

// ---------------------------------------------------------------------------
// pack_x: x (B,C,N) fp32 -> x^T (B,N,C) bf16
// ---------------------------------------------------------------------------
__global__ __launch_bounds__(256) void pack_x_kernel(
    const float* __restrict__ x, __nv_bfloat16* __restrict__ xt)
{
    __shared__ float t[32][33];
    const int b = blockIdx.z, c0 = blockIdx.y * 32, n0 = blockIdx.x * 32;
    const int tid = threadIdx.x;
    #pragma unroll
    for (int r = 0; r < 4; r++) {
        const int c = (tid >> 5) + r * 8;
        t[c][tid & 31] = x[((size_t)b * C_ + c0 + c) * N_ + n0 + (tid & 31)];
    }
    __syncthreads();
    #pragma unroll
    for (int r = 0; r < 4; r++) {
        const int n = (tid >> 5) + r * 8;
        xt[((size_t)b * N_ + n0 + n) * C_ + c0 + (tid & 31)] =
            __float2bfloat16(t[tid & 31][n]);
    }
}

// wv fp32 -> bf16
__global__ __launch_bounds__(256) void pack_w_kernel(
    const float* __restrict__ w, __nv_bfloat16* __restrict__ wb, int n)
{
    const int i = blockIdx.x * 256 + threadIdx.x;
    if (i < n) wb[i] = __float2bfloat16(w[i]);
}

// ---------------------------------------------------------------------------
// q/k projection (SIMT fp32, tiny) writing TRANSPOSED bf16 output (B,N,32)
// ---------------------------------------------------------------------------
__global__ __launch_bounds__(256) void projqk_kernel(
    const float* __restrict__ W, const float* __restrict__ bias,
    const float* __restrict__ x, __nv_bfloat16* __restrict__ outt)
{
    __shared__ float Ws[32][32];
    __shared__ float Xs[32][128];

    const int b = blockIdx.z, n0 = blockIdx.x * 128;
    const int tid = threadIdx.x;
    const int tr = tid >> 5, tc = tid & 31;
    const float* xb = x + (size_t)b * C_ * N_;

    float acc[4][4] = {};
    for (int c0 = 0; c0 < C_; c0 += 32) {
        {
            const int r = tid >> 3, k4 = (tid & 7) * 4;
            const float4 w4 = *(const float4*)(W + (size_t)r * C_ + c0 + k4);
            Ws[k4 + 0][r] = w4.x; Ws[k4 + 1][r] = w4.y;
            Ws[k4 + 2][r] = w4.z; Ws[k4 + 3][r] = w4.w;
        }
        #pragma unroll
        for (int ps = 0; ps < 4; ps++) {
            const int kk = ps * 8 + (tid >> 5);
            *(float4*)&Xs[kk][tc * 4] =
                *(const float4*)(xb + (size_t)(c0 + kk) * N_ + n0 + tc * 4);
        }
        __syncthreads();
        #pragma unroll
        for (int kk = 0; kk < 32; kk++) {
            const float4 wf = *(const float4*)&Ws[kk][tr * 4];
            const float4 xf = *(const float4*)&Xs[kk][tc * 4];
            acc[0][0] += wf.x * xf.x; acc[0][1] += wf.x * xf.y; acc[0][2] += wf.x * xf.z; acc[0][3] += wf.x * xf.w;
            acc[1][0] += wf.y * xf.x; acc[1][1] += wf.y * xf.y; acc[1][2] += wf.y * xf.z; acc[1][3] += wf.y * xf.w;
            acc[2][0] += wf.z * xf.x; acc[2][1] += wf.z * xf.y; acc[2][2] += wf.z * xf.z; acc[2][3] += wf.z * xf.w;
            acc[3][0] += wf.w * xf.x; acc[3][1] += wf.w * xf.y; acc[3][2] += wf.w * xf.z; acc[3][3] += wf.w * xf.w;
        }
        __syncthreads();
    }
    #pragma unroll
    for (int i = 0; i < 4; i++) {
        const int m = tr * 4 + i;
        const float bm = bias[m];
        #pragma unroll
        for (int j = 0; j < 4; j++) {
            const int n = n0 + tc * 4 + j;
            outt[((size_t)b * N_ + n) * D_ + m] = __float2bfloat16(acc[i][j] + bm);
        }
    }
}

// ---------------------------------------------------------------------------
// v projection (tensor core): v[b][m][n] = wv[m][:] . xt[b][n][:] + bv[m]
// BM=128 BN=128 BK=32, K=256. Output bf16.
// ---------------------------------------------------------------------------
__global__ __launch_bounds__(256) void projv_tc(
    const __nv_bfloat16* __restrict__ wv, const float* __restrict__ bv,
    const __nv_bfloat16* __restrict__ xt, __nv_bfloat16* __restrict__ v)
{
    __shared__ __align__(16) __nv_bfloat16 sm[4 * 128 * SMS];
    const int b = blockIdx.z, m0 = blockIdx.y * 128, n0 = blockIdx.x * 128;
    const int tid = threadIdx.x, lane = tid & 31, warp = tid >> 5;
    const int wm = warp & 1, wn = warp >> 1;
    const uint32_t sbase = smem_u32(sm);
    const int row = tid >> 2, c8 = (tid & 3) << 3;

    const __nv_bfloat16* A = wv + (size_t)(m0 + row) * C_ + c8;
    const __nv_bfloat16* Bm = xt + ((size_t)b * N_ + n0 + row) * C_ + c8;

    float acc[4][4][4] = {};

    // prefetch k-chunk 0
    {
        const uint32_t sa = sbase + (uint32_t)((row * SMS + c8) * 2);
        CP_ASYNC16(sa,                      A);
        CP_ASYNC16(sa + 64 * SMS * 2,       A + (size_t)64 * C_);
        CP_ASYNC16(sa + 128 * SMS * 2,      Bm);
        CP_ASYNC16(sa + (128 + 64) * SMS * 2, Bm + (size_t)64 * C_);
        CP_COMMIT();
    }
    #pragma unroll 1
    for (int it = 0; it < 8; it++) {
        CP_WAIT0(); __syncthreads();
        if (it < 7) {
            const int st = (it + 1) & 1, j0 = (it + 1) * 32;
            const uint32_t sa = sbase + (uint32_t)(st * 2 * 128 * SMS * 2 + (row * SMS + c8) * 2);
            CP_ASYNC16(sa,                       A + j0);
            CP_ASYNC16(sa + 64 * SMS * 2,        A + j0 + (size_t)64 * C_);
            CP_ASYNC16(sa + 128 * SMS * 2,       Bm + j0);
            CP_ASYNC16(sa + (128 + 64) * SMS * 2, Bm + j0 + (size_t)64 * C_);
            CP_COMMIT();
        }
        const uint32_t sA = sbase + (uint32_t)((it & 1) * 2 * 128 * SMS * 2);
        const uint32_t sB = sA + 128 * SMS * 2;
        mma_tile_step(sA, sB, 0,  lane, wm, wn, acc);
        mma_tile_step(sA, sB, 16, lane, wm, wn, acc);
        __syncthreads();
    }

    #pragma unroll
    for (int mt = 0; mt < 4; mt++)
        #pragma unroll
        for (int h = 0; h < 2; h++) {
            const int m = m0 + wm * 64 + mt * 16 + (lane >> 2) + h * 8;
            const float bm = bv[m];
            #pragma unroll
            for (int nt = 0; nt < 4; nt++) {
                const int n = n0 + wn * 32 + nt * 8 + ((lane & 3) << 1);
                __nv_bfloat162 o;
                o.x = __float2bfloat16(acc[mt][nt][h * 2 + 0] + bm);
                o.y = __float2bfloat16(acc[mt][nt][h * 2 + 1] + bm);
                *(__nv_bfloat162*)(v + ((size_t)b * C_ + m) * N_ + n) = o;
            }
        }
}

// ---------------------------------------------------------------------------
// energy (tensor core): e[b][i][j] = qt[b][i][:] . kt[b][j][:]   (K=32)
// ---------------------------------------------------------------------------
__global__ __launch_bounds__(256) void energy_tc(
    const __nv_bfloat16* __restrict__ qt, const __nv_bfloat16* __restrict__ kt,
    float* __restrict__ p)
{
    __shared__ __align__(16) __nv_bfloat16 sm[2 * 128 * SMS];
    const int b = blockIdx.z, i0 = blockIdx.y * 128, j0 = blockIdx.x * 128;
    const int tid = threadIdx.x, lane = tid & 31, warp = tid >> 5;
    const int wm = warp & 1, wn = warp >> 1;
    const int row = tid >> 2, c8 = (tid & 3) << 3;

    *(uint4*)&sm[row * SMS + c8] =
        *(const uint4*)(qt + ((size_t)b * N_ + i0 + row) * D_ + c8);
    *(uint4*)&sm[(row + 64) * SMS + c8] =
        *(const uint4*)(qt + ((size_t)b * N_ + i0 + row + 64) * D_ + c8);
    *(uint4*)&sm[(128 + row) * SMS + c8] =
        *(const uint4*)(kt + ((size_t)b * N_ + j0 + row) * D_ + c8);
    *(uint4*)&sm[(128 + row + 64) * SMS + c8] =
        *(const uint4*)(kt + ((size_t)b * N_ + j0 + row + 64) * D_ + c8);
    __syncthreads();

    float acc[4][4][4] = {};
    const uint32_t sA = smem_u32(sm), sB = sA + 128 * SMS * 2;
    mma_tile_step(sA, sB, 0,  lane, wm, wn, acc);
    mma_tile_step(sA, sB, 16, lane, wm, wn, acc);

    float* pb = p + (size_t)b * N_ * N_;
    #pragma unroll
    for (int mt = 0; mt < 4; mt++)
        #pragma unroll
        for (int h = 0; h < 2; h++) {
            const int i = i0 + wm * 64 + mt * 16 + (lane >> 2) + h * 8;
            #pragma unroll
            for (int nt = 0; nt < 4; nt++) {
                const int j = j0 + wn * 32 + nt * 8 + ((lane & 3) << 1);
                float2 o = { acc[mt][nt][h * 2 + 0], acc[mt][nt][h * 2 + 1] };
                *(float2*)(pb + (size_t)i * N_ + j) = o;
            }
        }
}

// ---------------------------------------------------------------------------
// softmax: fp32 logits in, bf16 probs out
// ---------------------------------------------------------------------------
__global__ __launch_bounds__(256) void softmax_kernel(
    const float* __restrict__ p, __nv_bfloat16* __restrict__ pbf)
{
    const size_t roff = ((size_t)blockIdx.y * N_ + blockIdx.x) * N_;
    const float* pr = p + roff;
    const int tid = threadIdx.x;

    float4 v0 = ((const float4*)pr)[tid];
    float4 v1 = ((const float4*)pr)[tid + 256];

    float m = fmaxf(fmaxf(fmaxf(v0.x, v0.y), fmaxf(v0.z, v0.w)),
                    fmaxf(fmaxf(v1.x, v1.y), fmaxf(v1.z, v1.w)));
    #pragma unroll
    for (int o = 16; o > 0; o >>= 1)
        m = fmaxf(m, __shfl_xor_sync(0xFFFFFFFFu, m, o));

    __shared__ float red[8];
    if ((tid & 31) == 0) red[tid >> 5] = m;
    __syncthreads();
    float bm = red[0];
    #pragma unroll
    for (int w = 1; w < 8; w++) bm = fmaxf(bm, red[w]);
    __syncthreads();

    float4 e0, e1;
    e0.x = __expf(v0.x - bm); e0.y = __expf(v0.y - bm);
    e0.z = __expf(v0.z - bm); e0.w = __expf(v0.w - bm);
    e1.x = __expf(v1.x - bm); e1.y = __expf(v1.y - bm);
    e1.z = __expf(v1.z - bm); e1.w = __expf(v1.w - bm);

    float s = e0.x + e0.y + e0.z + e0.w + e1.x + e1.y + e1.z + e1.w;
    #pragma unroll
    for (int o = 16; o > 0; o >>= 1)
        s += __shfl_xor_sync(0xFFFFFFFFu, s, o);
    if ((tid & 31) == 0) red[tid >> 5] = s;
    __syncthreads();
    float bs = 0.f;
    #pragma unroll
    for (int w = 0; w < 8; w++) bs += red[w];

    const float inv = 1.0f / bs;
    __nv_bfloat16* pw = pbf + roff;
    __nv_bfloat162 w0, w1;
    w0.x = __float2bfloat16(e0.x * inv); w0.y = __float2bfloat16(e0.y * inv);
    w1.x = __float2bfloat16(e0.z * inv); w1.y = __float2bfloat16(e0.w * inv);
    *(__nv_bfloat162*)(pw + tid * 4)     = w0;
    *(__nv_bfloat162*)(pw + tid * 4 + 2) = w1;
    w0.x = __float2bfloat16(e1.x * inv); w0.y = __float2bfloat16(e1.y * inv);
    w1.x = __float2bfloat16(e1.z * inv); w1.y = __float2bfloat16(e1.w * inv);
    *(__nv_bfloat162*)(pw + (tid + 256) * 4)     = w0;
    *(__nv_bfloat162*)(pw + (tid + 256) * 4 + 2) = w1;
}

// ---------------------------------------------------------------------------
// out (tensor core): out[b][m][i] = gamma * sum_j v[m][j] P[i][j] + x[b][m][i]
// BM=128 BN=128 BK=32, K=2048.
// ---------------------------------------------------------------------------
__global__ __launch_bounds__(256) void out_tc(
    const __nv_bfloat16* __restrict__ v, const __nv_bfloat16* __restrict__ p,
    const float* __restrict__ x, const float* __restrict__ gamma,
    float* __restrict__ out)
{
    __shared__ __align__(16) __nv_bfloat16 sm[4 * 128 * SMS];
    const int b = blockIdx.z, m0 = blockIdx.y * 128, i0 = blockIdx.x * 128;
    const int tid = threadIdx.x, lane = tid & 31, warp = tid >> 5;
    const int wm = warp & 1, wn = warp >> 1;
    const uint32_t sbase = smem_u32(sm);
    const int row = tid >> 2, c8 = (tid & 3) << 3;

    const __nv_bfloat16* A = v + ((size_t)b * C_ + m0 + row) * N_ + c8;
    const __nv_bfloat16* Bm = p + ((size_t)b * N_ + i0 + row) * N_ + c8;

    float acc[4][4][4] = {};

    {
        const uint32_t sa = sbase + (uint32_t)((row * SMS + c8) * 2);
        CP_ASYNC16(sa,                        A);
        CP_ASYNC16(sa + 64 * SMS * 2,         A + (size_t)64 * N_);
        CP_ASYNC16(sa + 128 * SMS * 2,        Bm);
        CP_ASYNC16(sa + (128 + 64) * SMS * 2, Bm + (size_t)64 * N_);
        CP_COMMIT();
    }
    #pragma unroll 1
    for (int it = 0; it < 64; it++) {
        CP_WAIT0(); __syncthreads();
        if (it < 63) {
            const int st = (it + 1) & 1, j0 = (it + 1) * 32;
            const uint32_t sa = sbase + (uint32_t)(st * 2 * 128 * SMS * 2 + (row * SMS + c8) * 2);
            CP_ASYNC16(sa,                        A + j0);
            CP_ASYNC16(sa + 64 * SMS * 2,         A + j0 + (size_t)64 * N_);
            CP_ASYNC16(sa + 128 * SMS * 2,        Bm + j0);
            CP_ASYNC16(sa + (128 + 64) * SMS * 2, Bm + j0 + (size_t)64 * N_);
            CP_COMMIT();
        }
        const uint32_t sA = sbase + (uint32_t)((it & 1) * 2 * 128 * SMS * 2);
        const uint32_t sB = sA + 128 * SMS * 2;
        mma_tile_step(sA, sB, 0,  lane, wm, wn, acc);
        mma_tile_step(sA, sB, 16, lane, wm, wn, acc);
        __syncthreads();
    }

    const float g = *gamma;
    #pragma unroll
    for (int mt = 0; mt < 4; mt++)
        #pragma unroll
        for (int h = 0; h < 2; h++) {
            const int m = m0 + wm * 64 + mt * 16 + (lane >> 2) + h * 8;
            #pragma unroll
            for (int nt = 0; nt < 4; nt++) {
                const int n = i0 + wn * 32 + nt * 8 + ((lane & 3) << 1);
                const size_t base = ((size_t)b * C_ + m) * N_ + n;
                const float2 xv = *(const float2*)(x + base);
                float2 o;
                o.x = g * acc[mt][nt][h * 2 + 0] + xv.x;
                o.y = g * acc[mt][nt][h * 2 + 1] + xv.y;
                *(float2*)(out + base) = o;
            }
        }
}

// ---------------------------------------------------------------------------
// Launch
// ---------------------------------------------------------------------------
extern "C" void kernel_launch(void* const* d_in, const int* in_sizes, int n_in,
                              void* d_out, int out_size)
{
    const float* x     = (const float*)d_in[0];
    const float* wq    = (const float*)d_in[1];
    const float* bq    = (const float*)d_in[2];
    const float* wk    = (const float*)d_in[3];
    const float* bk    = (const float*)d_in[4];
    const float* wv    = (const float*)d_in[5];
    const float* bv    = (const float*)d_in[6];
    const float* gamma = (const float*)d_in[7];
    float* out = (float*)d_out;

    float *pp;
    __nv_bfloat16 *ppbf, *pxt, *pqt, *pkt, *pvbf, *pwvbf;
    cudaGetSymbolAddress((void**)&pp,    g_p);
    cudaGetSymbolAddress((void**)&ppbf,  g_pbf);
    cudaGetSymbolAddress((void**)&pxt,   g_xt);
    cudaGetSymbolAddress((void**)&pqt,   g_qt);
    cudaGetSymbolAddress((void**)&pkt,   g_kt);
    cudaGetSymbolAddress((void**)&pvbf,  g_vbf);
    cudaGetSymbolAddress((void**)&pwvbf, g_wvbf);

    pack_x_kernel<<<dim3(N_ / 32, C_ / 32, B_), 256>>>(x, pxt);
    pack_w_kernel<<<(C_ * C_ + 255) / 256, 256>>>(wv, pwvbf, C_ * C_);

    projqk_kernel<<<dim3(N_ / 128, 1, B_), 256>>>(wq, bq, x, pqt);
    projqk_kernel<<<dim3(N_ / 128, 1, B_), 256>>>(wk, bk, x, pkt);
    projv_tc<<<dim3(N_ / 128, C_ / 128, B_), 256>>>(pwvbf, bv, pxt, pvbf);

    energy_tc<<<dim3(N_ / 128, N_ / 128, B_), 256>>>(pqt, pkt, pp);
    softmax_kernel<<<dim3(N_, B_), 256>>>(pp, ppbf);
    out_tc<<<dim3(N_ / 128, C_ / 128, B_), 256>>>(pvbf, ppbf, x, gamma, out);
}

// round 3
// speedup vs baseline: 4.7515x; 1.3302x over previous
#include <cuda_runtime.h>
#include <cuda_bf16.h>
#include <cstdint>

#define B_  8
#define C_  256
#define N_  2048
#define D_  32
#define BJ  64

// ---------------------------------------------------------------------------
// Device-global scratch (allocation-free)
// ---------------------------------------------------------------------------
__device__ __nv_bfloat16  g_xt [(size_t)B_ * N_ * C_];   // x^T  (B,N,C) bf16
__device__ __nv_bfloat16  g_qt [(size_t)B_ * N_ * D_];   // q^T  (B,N,D) bf16
__device__ __nv_bfloat16  g_kt [(size_t)B_ * N_ * D_];   // k^T  (B,N,D) bf16
__device__ __nv_bfloat16  g_vbf[(size_t)B_ * C_ * N_];   // v    (B,C,N) bf16
__device__ __nv_bfloat16  g_wvbf[C_ * C_];               // wv bf16

// ---------------------------------------------------------------------------
// PTX helpers
// ---------------------------------------------------------------------------
__device__ __forceinline__ uint32_t smem_u32(const void* p) {
    uint32_t a;
    asm("{ .reg .u64 t; cvta.to.shared.u64 t, %1; cvt.u32.u64 %0, t; }"
        : "=r"(a) : "l"(p));
    return a;
}
__device__ __forceinline__ void ldm_x4(uint32_t* r, uint32_t addr) {
    asm volatile("ldmatrix.sync.aligned.m8n8.x4.shared.b16 {%0,%1,%2,%3}, [%4];\n"
        : "=r"(r[0]), "=r"(r[1]), "=r"(r[2]), "=r"(r[3]) : "r"(addr));
}
__device__ __forceinline__ void mma_bf16(float* d, const uint32_t* a, const uint32_t* b) {
    asm volatile(
        "mma.sync.aligned.m16n8k16.row.col.f32.bf16.bf16.f32 "
        "{%0,%1,%2,%3},{%4,%5,%6,%7},{%8,%9},{%0,%1,%2,%3};\n"
        : "+f"(d[0]), "+f"(d[1]), "+f"(d[2]), "+f"(d[3])
        : "r"(a[0]), "r"(a[1]), "r"(a[2]), "r"(a[3]), "r"(b[0]), "r"(b[1]));
}
__device__ __forceinline__ uint32_t packbf2(float a, float b) {
    __nv_bfloat162 h = __floats2bfloat162_rn(a, b);
    return *(uint32_t*)&h;
}
#define CP_ASYNC16(saddr, gptr) \
    asm volatile("cp.async.cg.shared.global [%0], [%1], 16;\n" :: "r"(saddr), "l"(gptr))
#define CP_COMMIT() asm volatile("cp.async.commit_group;\n")
#define CP_WAIT0()  asm volatile("cp.async.wait_group 0;\n")

#define SMS 40   // 32 data + 8 pad bf16 (conflict-free ldmatrix)
#define VMS 72   // 64 data + 8 pad bf16

// One K=16 step of a 64x32 warp tile (projv mainloop helper)
__device__ __forceinline__ void mma_tile_step(
    uint32_t sA, uint32_t sB, int kk, int lane, int wm, int wn, float acc[4][4][4])
{
    const int rrow  = lane & 15;
    const int chalf = (lane >> 4) << 3;
    uint32_t a[4][4], bq[2][4];
    #pragma unroll
    for (int mt = 0; mt < 4; mt++)
        ldm_x4(a[mt], sA + (uint32_t)(((wm * 64 + mt * 16 + rrow) * SMS + kk + chalf) * 2));
    #pragma unroll
    for (int np = 0; np < 2; np++)
        ldm_x4(bq[np], sB + (uint32_t)(((wn * 32 + np * 16 + rrow) * SMS + kk + chalf) * 2));
    #pragma unroll
    for (int mt = 0; mt < 4; mt++)
        #pragma unroll
        for (int nt = 0; nt < 4; nt++) {
            uint32_t bb[2] = { bq[nt >> 1][nt & 1], bq[nt >> 1][(nt & 1) + 2] };
            mma_bf16(acc[mt][nt], a[mt], bb);
        }
}

// ---------------------------------------------------------------------------
// pack_x: x (B,C,N) fp32 -> x^T (B,N,C) bf16
// ---------------------------------------------------------------------------
__global__ __launch_bounds__(256) void pack_x_kernel(
    const float* __restrict__ x, __nv_bfloat16* __restrict__ xt)
{
    __shared__ float t[32][33];
    const int b = blockIdx.z, c0 = blockIdx.y * 32, n0 = blockIdx.x * 32;
    const int tid = threadIdx.x;
    #pragma unroll
    for (int r = 0; r < 4; r++) {
        const int c = (tid >> 5) + r * 8;
        t[c][tid & 31] = x[((size_t)b * C_ + c0 + c) * N_ + n0 + (tid & 31)];
    }
    __syncthreads();
    #pragma unroll
    for (int r = 0; r < 4; r++) {
        const int n = (tid >> 5) + r * 8;
        xt[((size_t)b * N_ + n0 + n) * C_ + c0 + (tid & 31)] =
            __float2bfloat16(t[tid & 31][n]);
    }
}

__global__ __launch_bounds__(256) void pack_w_kernel(
    const float* __restrict__ w, __nv_bfloat16* __restrict__ wb, int n)
{
    const int i = blockIdx.x * 256 + threadIdx.x;
    if (i < n) wb[i] = __float2bfloat16(w[i]);
}

// ---------------------------------------------------------------------------
// Fused q+k projection (fp32 SIMT), transposed bf16 outputs (B,N,32).
// BM=64 (rows 0-31: wq, 32-63: wk), BN=64, K=256. grid=(N/64,1,B), 256 thr.
// ---------------------------------------------------------------------------
__global__ __launch_bounds__(256) void projqk_kernel(
    const float* __restrict__ wq, const float* __restrict__ bq,
    const float* __restrict__ wk, const float* __restrict__ bk,
    const float* __restrict__ x,
    __nv_bfloat16* __restrict__ qt, __nv_bfloat16* __restrict__ kt)
{
    __shared__ float Ws[32][64];   // [kk][m]
    __shared__ float Xs[32][64];   // [kk][n]

    const int b = blockIdx.z, n0 = blockIdx.x * 64;
    const int tid = threadIdx.x;
    const int tr = tid >> 4, tc = tid & 15;
    const float* xb = x + (size_t)b * C_ * N_;

    float acc[4][4] = {};
    for (int c0 = 0; c0 < C_; c0 += 32) {
        {   // W tile: m = tid>>2 (0..63), two float4s along k
            const int m = tid >> 2;
            const float* wrow = (m < 32) ? (wq + (size_t)m * C_)
                                         : (wk + (size_t)(m - 32) * C_);
            #pragma unroll
            for (int h = 0; h < 2; h++) {
                const int k4 = (tid & 3) * 4 + h * 16;
                const float4 w4 = *(const float4*)(wrow + c0 + k4);
                Ws[k4 + 0][m] = w4.x; Ws[k4 + 1][m] = w4.y;
                Ws[k4 + 2][m] = w4.z; Ws[k4 + 3][m] = w4.w;
            }
        }
        {   // X tile: kk = tid>>3 (0..31), 8 floats along n
            const int kk = tid >> 3, nn = (tid & 7) * 8;
            *(float4*)&Xs[kk][nn] =
                *(const float4*)(xb + (size_t)(c0 + kk) * N_ + n0 + nn);
            *(float4*)&Xs[kk][nn + 4] =
                *(const float4*)(xb + (size_t)(c0 + kk) * N_ + n0 + nn + 4);
        }
        __syncthreads();
        #pragma unroll
        for (int kk = 0; kk < 32; kk++) {
            const float4 wf = *(const float4*)&Ws[kk][tr * 4];
            const float4 xf = *(const float4*)&Xs[kk][tc * 4];
            acc[0][0] += wf.x * xf.x; acc[0][1] += wf.x * xf.y; acc[0][2] += wf.x * xf.z; acc[0][3] += wf.x * xf.w;
            acc[1][0] += wf.y * xf.x; acc[1][1] += wf.y * xf.y; acc[1][2] += wf.y * xf.z; acc[1][3] += wf.y * xf.w;
            acc[2][0] += wf.z * xf.x; acc[2][1] += wf.z * xf.y; acc[2][2] += wf.z * xf.z; acc[2][3] += wf.z * xf.w;
            acc[3][0] += wf.w * xf.x; acc[3][1] += wf.w * xf.y; acc[3][2] += wf.w * xf.z; acc[3][3] += wf.w * xf.w;
        }
        __syncthreads();
    }

    const int mbase = tr * 4;
    const bool isq = (mbase < 32);
    __nv_bfloat16* dst = isq ? qt : kt;
    const float* bias = isq ? bq : bk;
    const int mo = isq ? mbase : (mbase - 32);
    const float b0v = bias[mo], b1v = bias[mo + 1], b2v = bias[mo + 2], b3v = bias[mo + 3];
    #pragma unroll
    for (int j = 0; j < 4; j++) {
        const int n = n0 + tc * 4 + j;
        __nv_bfloat16* o = dst + ((size_t)b * N_ + n) * D_ + mo;
        *(__nv_bfloat162*)(o)     = __floats2bfloat162_rn(acc[0][j] + b0v, acc[1][j] + b1v);
        *(__nv_bfloat162*)(o + 2) = __floats2bfloat162_rn(acc[2][j] + b2v, acc[3][j] + b3v);
    }
}

// ---------------------------------------------------------------------------
// v projection (tensor core): v[b][m][n] = wv[m][:] . xt[b][n][:] + bv[m]
// ---------------------------------------------------------------------------
__global__ __launch_bounds__(256) void projv_tc(
    const __nv_bfloat16* __restrict__ wv, const float* __restrict__ bv,
    const __nv_bfloat16* __restrict__ xt, __nv_bfloat16* __restrict__ v)
{
    __shared__ __align__(16) __nv_bfloat16 sm[4 * 128 * SMS];
    const int b = blockIdx.z, m0 = blockIdx.y * 128, n0 = blockIdx.x * 128;
    const int tid = threadIdx.x, lane = tid & 31, warp = tid >> 5;
    const int wm = warp & 1, wn = warp >> 1;
    const uint32_t sbase = smem_u32(sm);
    const int row = tid >> 2, c8 = (tid & 3) << 3;

    const __nv_bfloat16* A = wv + (size_t)(m0 + row) * C_ + c8;
    const __nv_bfloat16* Bm = xt + ((size_t)b * N_ + n0 + row) * C_ + c8;

    float acc[4][4][4] = {};
    {
        const uint32_t sa = sbase + (uint32_t)((row * SMS + c8) * 2);
        CP_ASYNC16(sa,                        A);
        CP_ASYNC16(sa + 64 * SMS * 2,         A + (size_t)64 * C_);
        CP_ASYNC16(sa + 128 * SMS * 2,        Bm);
        CP_ASYNC16(sa + (128 + 64) * SMS * 2, Bm + (size_t)64 * C_);
        CP_COMMIT();
    }
    #pragma unroll 1
    for (int it = 0; it < 8; it++) {
        CP_WAIT0(); __syncthreads();
        if (it < 7) {
            const int st = (it + 1) & 1, j0 = (it + 1) * 32;
            const uint32_t sa = sbase + (uint32_t)(st * 2 * 128 * SMS * 2 + (row * SMS + c8) * 2);
            CP_ASYNC16(sa,                        A + j0);
            CP_ASYNC16(sa + 64 * SMS * 2,         A + j0 + (size_t)64 * C_);
            CP_ASYNC16(sa + 128 * SMS * 2,        Bm + j0);
            CP_ASYNC16(sa + (128 + 64) * SMS * 2, Bm + j0 + (size_t)64 * C_);
            CP_COMMIT();
        }
        const uint32_t sA = sbase + (uint32_t)((it & 1) * 2 * 128 * SMS * 2);
        const uint32_t sB = sA + 128 * SMS * 2;
        mma_tile_step(sA, sB, 0,  lane, wm, wn, acc);
        mma_tile_step(sA, sB, 16, lane, wm, wn, acc);
        __syncthreads();
    }
    #pragma unroll
    for (int mt = 0; mt < 4; mt++)
        #pragma unroll
        for (int h = 0; h < 2; h++) {
            const int m = m0 + wm * 64 + mt * 16 + (lane >> 2) + h * 8;
            const float bm = bv[m];
            #pragma unroll
            for (int nt = 0; nt < 4; nt++) {
                const int n = n0 + wn * 32 + nt * 8 + ((lane & 3) << 1);
                __nv_bfloat162 o;
                o.x = __float2bfloat16(acc[mt][nt][h * 2 + 0] + bm);
                o.y = __float2bfloat16(acc[mt][nt][h * 2 + 1] + bm);
                *(__nv_bfloat162*)(v + ((size_t)b * C_ + m) * N_ + n) = o;
            }
        }
}

// ---------------------------------------------------------------------------
// Flash attention: energy + softmax + out fused.
// Block: 128 i-rows x 128 c-chunk, 8 warps (warp = 16 i-rows), BJ=64 key tile.
// grid = (C/128, N/128, B). Dynamic smem.
//   S = Q K^T (K=32), online softmax in regs, O += P V^T with fragment reuse.
// Epilogue: out[b][c][i] = gamma * O[i][c] / l[i] + x[b][c][i]
// ---------------------------------------------------------------------------
__global__ __launch_bounds__(256) void flash_tc(
    const __nv_bfloat16* __restrict__ qt, const __nv_bfloat16* __restrict__ kt,
    const __nv_bfloat16* __restrict__ v, const float* __restrict__ x,
    const float* __restrict__ gamma, float* __restrict__ out)
{
    extern __shared__ __align__(16) char smem_raw[];
    __nv_bfloat16* sQ = (__nv_bfloat16*)smem_raw;            // 128*40
    __nv_bfloat16* sK = sQ + 128 * SMS;                      // 2*64*40
    __nv_bfloat16* sV = sK + 2 * 64 * SMS;                   // 2*128*72
    float* sO = (float*)smem_raw;                            // epilogue (128*132)

    const int b  = blockIdx.z;
    const int i0 = blockIdx.y * 128;
    const int c0 = blockIdx.x * 128;
    const int tid = threadIdx.x, lane = tid & 31, warp = tid >> 5;
    const int rrow = lane & 15, chalf = (lane >> 4) << 3;

    const __nv_bfloat16* Qg = qt + ((size_t)b * N_ + i0) * D_;
    const __nv_bfloat16* Kg = kt + (size_t)b * N_ * D_;
    const __nv_bfloat16* Vg = v  + ((size_t)b * C_ + c0) * N_;

    const uint32_t sQa = smem_u32(sQ);
    const uint32_t sKa = smem_u32(sK);
    const uint32_t sVa = smem_u32(sV);

    // prologue: Q (whole), K tile 0, V tile 0
    {
        #pragma unroll
        for (int p = 0; p < 2; p++) {
            const int idx = tid + p * 256, r = idx >> 2, s = (idx & 3) * 8;
            CP_ASYNC16(sQa + (uint32_t)((r * SMS + s) * 2), Qg + (size_t)r * D_ + s);
        }
        { const int r = tid >> 2, s = (tid & 3) * 8;
          CP_ASYNC16(sKa + (uint32_t)((r * SMS + s) * 2), Kg + (size_t)r * D_ + s); }
        #pragma unroll
        for (int p = 0; p < 4; p++) {
            const int idx = tid + p * 256, r = idx >> 3, s = (idx & 7) * 8;
            CP_ASYNC16(sVa + (uint32_t)((r * VMS + s) * 2), Vg + (size_t)r * N_ + s);
        }
        CP_COMMIT();
    }

    float accO[16][4] = {};
    float m_r = -INFINITY, m_r8 = -INFINITY, l_r = 0.f, l_r8 = 0.f;
    uint32_t qf[2][4];

    #pragma unroll 1
    for (int it = 0; it < N_ / BJ; it++) {
        CP_WAIT0(); __syncthreads();
        if (it == 0) {
            ldm_x4(qf[0], sQa + (uint32_t)(((warp * 16 + rrow) * SMS + 0  + chalf) * 2));
            ldm_x4(qf[1], sQa + (uint32_t)(((warp * 16 + rrow) * SMS + 16 + chalf) * 2));
        }
        if (it < N_ / BJ - 1) {
            const int st = (it + 1) & 1, j1 = (it + 1) * BJ;
            { const int r = tid >> 2, s = (tid & 3) * 8;
              CP_ASYNC16(sKa + (uint32_t)((st * 64 * SMS + r * SMS + s) * 2),
                         Kg + (size_t)(j1 + r) * D_ + s); }
            #pragma unroll
            for (int p = 0; p < 4; p++) {
                const int idx = tid + p * 256, r = idx >> 3, s = (idx & 7) * 8;
                CP_ASYNC16(sVa + (uint32_t)((st * 128 * VMS + r * VMS + s) * 2),
                           Vg + (size_t)r * N_ + j1 + s);
            }
            CP_COMMIT();
        }
        const uint32_t kb = sKa + (uint32_t)((it & 1) * 64 * SMS * 2);
        const uint32_t vb = sVa + (uint32_t)((it & 1) * 128 * VMS * 2);

        // ---- S = Q K^T (warp: 16i x 64j) ----
        float accS[8][4] = {};
        #pragma unroll
        for (int jt = 0; jt < 4; jt++) {
            uint32_t b0[4], b1[4];
            ldm_x4(b0, kb + (uint32_t)(((jt * 16 + rrow) * SMS + 0  + chalf) * 2));
            ldm_x4(b1, kb + (uint32_t)(((jt * 16 + rrow) * SMS + 16 + chalf) * 2));
            #pragma unroll
            for (int np = 0; np < 2; np++) {
                uint32_t bb0[2] = { b0[np], b0[np + 2] };
                uint32_t bb1[2] = { b1[np], b1[np + 2] };
                mma_bf16(accS[jt * 2 + np], qf[0], bb0);
                mma_bf16(accS[jt * 2 + np], qf[1], bb1);
            }
        }

        // ---- online softmax (rows r=lane>>2, r+8) ----
        float mx0 = -INFINITY, mx1 = -INFINITY;
        #pragma unroll
        for (int t = 0; t < 8; t++) {
            mx0 = fmaxf(mx0, fmaxf(accS[t][0], accS[t][1]));
            mx1 = fmaxf(mx1, fmaxf(accS[t][2], accS[t][3]));
        }
        mx0 = fmaxf(mx0, __shfl_xor_sync(0xFFFFFFFFu, mx0, 1));
        mx0 = fmaxf(mx0, __shfl_xor_sync(0xFFFFFFFFu, mx0, 2));
        mx1 = fmaxf(mx1, __shfl_xor_sync(0xFFFFFFFFu, mx1, 1));
        mx1 = fmaxf(mx1, __shfl_xor_sync(0xFFFFFFFFu, mx1, 2));

        const float mn0 = fmaxf(m_r, mx0), mn1 = fmaxf(m_r8, mx1);
        const float al0 = __expf(m_r - mn0), al1 = __expf(m_r8 - mn1);
        m_r = mn0; m_r8 = mn1;

        float sum0 = 0.f, sum1 = 0.f;
        uint32_t pf[4][4];
        #pragma unroll
        for (int t = 0; t < 8; t++) {
            const float p0 = __expf(accS[t][0] - mn0);
            const float p1 = __expf(accS[t][1] - mn0);
            const float p2 = __expf(accS[t][2] - mn1);
            const float p3 = __expf(accS[t][3] - mn1);
            sum0 += p0 + p1; sum1 += p2 + p3;
            const int ks = t >> 1;
            if ((t & 1) == 0) { pf[ks][0] = packbf2(p0, p1); pf[ks][1] = packbf2(p2, p3); }
            else              { pf[ks][2] = packbf2(p0, p1); pf[ks][3] = packbf2(p2, p3); }
        }
        sum0 += __shfl_xor_sync(0xFFFFFFFFu, sum0, 1);
        sum0 += __shfl_xor_sync(0xFFFFFFFFu, sum0, 2);
        sum1 += __shfl_xor_sync(0xFFFFFFFFu, sum1, 1);
        sum1 += __shfl_xor_sync(0xFFFFFFFFu, sum1, 2);
        l_r  = l_r  * al0 + sum0;
        l_r8 = l_r8 * al1 + sum1;

        #pragma unroll
        for (int t = 0; t < 16; t++) {
            accO[t][0] *= al0; accO[t][1] *= al0;
            accO[t][2] *= al1; accO[t][3] *= al1;
        }

        // ---- O += P V^T (warp: 16i x 128c, k=64) ----
        #pragma unroll
        for (int ks = 0; ks < 4; ks++) {
            #pragma unroll
            for (int cg = 0; cg < 8; cg++) {
                uint32_t vb4[4];
                ldm_x4(vb4, vb + (uint32_t)(((cg * 16 + rrow) * VMS + ks * 16 + chalf) * 2));
                #pragma unroll
                for (int np = 0; np < 2; np++) {
                    uint32_t bb[2] = { vb4[np], vb4[np + 2] };
                    mma_bf16(accO[cg * 2 + np], pf[ks], bb);
                }
            }
        }
        __syncthreads();
    }

    // ---- epilogue: normalize, transpose through smem, residual+gamma ----
    const float il0 = 1.f / l_r, il1 = 1.f / l_r8;
    #pragma unroll
    for (int t = 0; t < 16; t++) {
        const int c = t * 8 + (lane & 3) * 2;
        const int i = warp * 16 + (lane >> 2);
        sO[(size_t)c * 132 + i]           = accO[t][0] * il0;
        sO[(size_t)(c + 1) * 132 + i]     = accO[t][1] * il0;
        sO[(size_t)c * 132 + i + 8]       = accO[t][2] * il1;
        sO[(size_t)(c + 1) * 132 + i + 8] = accO[t][3] * il1;
    }
    __syncthreads();
    const float g = *gamma;
    #pragma unroll
    for (int rep = 0; rep < 16; rep++) {
        const int idx = rep * 256 + tid;
        const int c = idx >> 5, i4 = (idx & 31) * 4;
        const size_t base = ((size_t)b * C_ + c0 + c) * N_ + i0 + i4;
        const float4 xv = *(const float4*)(x + base);
        const float4 ov = *(const float4*)&sO[(size_t)c * 132 + i4];
        float4 o;
        o.x = g * ov.x + xv.x; o.y = g * ov.y + xv.y;
        o.z = g * ov.z + xv.z; o.w = g * ov.w + xv.w;
        *(float4*)(out + base) = o;
    }
}

// ---------------------------------------------------------------------------
// Launch
// ---------------------------------------------------------------------------
extern "C" void kernel_launch(void* const* d_in, const int* in_sizes, int n_in,
                              void* d_out, int out_size)
{
    const float* x     = (const float*)d_in[0];
    const float* wq    = (const float*)d_in[1];
    const float* bq    = (const float*)d_in[2];
    const float* wk    = (const float*)d_in[3];
    const float* bk    = (const float*)d_in[4];
    const float* wv    = (const float*)d_in[5];
    const float* bv    = (const float*)d_in[6];
    const float* gamma = (const float*)d_in[7];
    float* out = (float*)d_out;

    __nv_bfloat16 *pxt, *pqt, *pkt, *pvbf, *pwvbf;
    cudaGetSymbolAddress((void**)&pxt,   g_xt);
    cudaGetSymbolAddress((void**)&pqt,   g_qt);
    cudaGetSymbolAddress((void**)&pkt,   g_kt);
    cudaGetSymbolAddress((void**)&pvbf,  g_vbf);
    cudaGetSymbolAddress((void**)&pwvbf, g_wvbf);

    // flash dynamic smem: max(mainloop 57344, epilogue 128*132*4=67584)
    static bool attr_set = false;
    if (!attr_set) {
        cudaFuncSetAttribute(flash_tc, cudaFuncAttributeMaxDynamicSharedMemorySize, 69632);
        attr_set = true;
    }

    pack_x_kernel<<<dim3(N_ / 32, C_ / 32, B_), 256>>>(x, pxt);
    pack_w_kernel<<<(C_ * C_ + 255) / 256, 256>>>(wv, pwvbf, C_ * C_);

    projqk_kernel<<<dim3(N_ / 64, 1, B_), 256>>>(wq, bq, wk, bk, x, pqt, pkt);
    projv_tc<<<dim3(N_ / 128, C_ / 128, B_), 256>>>(pwvbf, bv, pxt, pvbf);

    flash_tc<<<dim3(C_ / 128, N_ / 128, B_), 256, 69632>>>(pqt, pkt, pvbf, x, gamma, out);
}